// round 5
// baseline (speedup 1.0000x reference)
#include <cuda_runtime.h>

// Fixed problem shapes (from reference setup_inputs)
#define BB 4
#define NN 16384
#define EE 262144      // 2^18
#define FF 64
#define E_SHIFT 18

#define EXP_CLAMP 1000000.0f
#define DENOM_EPS 1e-10f
#define LRELU_ALPHA 0.01f

// Scratch (device globals; no allocation allowed)
__device__ float g_Wh[BB * NN * FF];     // 16.8 MB
__device__ float g_s1[BB * NN];
__device__ float g_s2[BB * NN];
__device__ float g_denom[BB * NN];
__device__ float g_xexp[BB * EE];

// ---------------------------------------------------------------------------
// Init: zero output, denom = eps
// ---------------------------------------------------------------------------
__global__ void init_kernel(float4* __restrict__ out4) {
    int i = blockIdx.x * blockDim.x + threadIdx.x;
    const int total4 = BB * NN * FF / 4;   // 1,048,576
    if (i < total4) out4[i] = make_float4(0.f, 0.f, 0.f, 0.f);
    if (i < BB * NN) g_denom[i] = DENOM_EPS;
}

// ---------------------------------------------------------------------------
// GEMM: Wh[b,n,o] = sum_f h[b,n,f] * W[o,f], fused s1/s2 epilogue.
// Block: 512 threads, 32 rows/block, 16 threads per row, 4 cols per thread.
// ---------------------------------------------------------------------------
__global__ __launch_bounds__(512) void gemm_kernel(
    const float* __restrict__ h,
    const float* __restrict__ W,
    const float* __restrict__ a)
{
    __shared__ __align__(16) float Wsh[64 * 68];  // [f][o] transposed, row pad 68
    __shared__ float hsh[32][65];                 // padded rows

    const int t = threadIdx.x;
    const int base = blockIdx.x * 32;             // row base within B*N

    // Load W transposed: Wsh[f*68 + o] = W[o*64 + f]
    // (strided global reads, conflict-free smem writes; W is tiny & L1/L2 hot)
    for (int i = t; i < 4096; i += 512) {
        int f = i >> 6, o = i & 63;
        Wsh[f * 68 + o] = W[o * 64 + f];
    }
    // Load 32 h rows (coalesced)
    for (int i = t; i < 2048; i += 512) {
        int r = i >> 6, f = i & 63;
        hsh[r][f] = h[(base + r) * 64 + f];
    }
    __syncthreads();

    const int r  = t >> 4;          // 0..31
    const int cg = (t & 15) << 2;   // 0,4,...,60

    float a0 = 0.f, a1 = 0.f, a2 = 0.f, a3 = 0.f;
#pragma unroll
    for (int f = 0; f < 64; f++) {
        float hv = hsh[r][f];
        float4 w = *(const float4*)&Wsh[f * 68 + cg];
        a0 += hv * w.x; a1 += hv * w.y; a2 += hv * w.z; a3 += hv * w.w;
    }

    const int row = base + r;
    *(float4*)&g_Wh[row * 64 + cg] = make_float4(a0, a1, a2, a3);

    // s1 = dot(Wh[row], a[0:64]), s2 = dot(Wh[row], a[64:128])
    float s1 = a0 * a[cg] + a1 * a[cg + 1] + a2 * a[cg + 2] + a3 * a[cg + 3];
    float s2 = a0 * a[64 + cg] + a1 * a[64 + cg + 1] + a2 * a[64 + cg + 2] + a3 * a[64 + cg + 3];
#pragma unroll
    for (int off = 8; off > 0; off >>= 1) {
        s1 += __shfl_down_sync(0xffffffffu, s1, off, 16);
        s2 += __shfl_down_sync(0xffffffffu, s2, off, 16);
    }
    if ((t & 15) == 0) {
        g_s1[row] = s1;
        g_s2[row] = s2;
    }
}

// ---------------------------------------------------------------------------
// Edge pass: x_exp + denom accumulation. One thread per (b,e).
// ---------------------------------------------------------------------------
__global__ void edge_kernel(
    const int* __restrict__ edge,
    const int* __restrict__ edge_num,
    const float* __restrict__ ew)
{
    int idx = blockIdx.x * blockDim.x + threadIdx.x;
    if (idx >= BB * EE) return;
    int b = idx >> E_SHIFT;
    int e = idx & (EE - 1);

    float x = 0.f;
    if (e < edge_num[b]) {
        int2 pr = ((const int2*)edge)[idx];     // {ctr, nbr}
        float z = ew[idx] * (g_s1[b * NN + pr.x] + g_s2[b * NN + pr.y]);
        z = (z > 0.f) ? z : LRELU_ALPHA * z;    // leaky relu
        x = fminf(__expf(z), EXP_CLAMP);        // clip(exp, 0, 1e6)
        atomicAdd(&g_denom[b * NN + pr.x], x);
    }
    g_xexp[idx] = x;
}

// ---------------------------------------------------------------------------
// Scatter: out[b, ctr, :] += (x/denom[ctr]) * Wh[b, nbr, :]
// 16 lanes per edge, 4 floats per lane (float4 gather + 4 scalar RED).
// ---------------------------------------------------------------------------
__global__ __launch_bounds__(256) void scatter_kernel(
    const int* __restrict__ edge,
    float* __restrict__ out)
{
    int gt = blockIdx.x * blockDim.x + threadIdx.x;
    int eidx = gt >> 4;
    if (eidx >= BB * EE) return;

    float x = g_xexp[eidx];
    if (x == 0.f) return;                       // masked or underflowed edge

    int lane = gt & 15;
    int b = eidx >> E_SHIFT;
    int2 pr = ((const int2*)edge)[eidx];        // {ctr, nbr}

    float att = x / g_denom[b * NN + pr.x];
    float4 wh = *(const float4*)&g_Wh[(b * NN + pr.y) * 64 + lane * 4];
    float* o = &out[(b * NN + pr.x) * 64 + lane * 4];
    atomicAdd(o + 0, att * wh.x);
    atomicAdd(o + 1, att * wh.y);
    atomicAdd(o + 2, att * wh.z);
    atomicAdd(o + 3, att * wh.w);
}

// ---------------------------------------------------------------------------
// Final relu
// ---------------------------------------------------------------------------
__global__ void relu_kernel(float4* __restrict__ out4) {
    int i = blockIdx.x * blockDim.x + threadIdx.x;
    const int total4 = BB * NN * FF / 4;
    if (i < total4) {
        float4 v = out4[i];
        v.x = fmaxf(v.x, 0.f); v.y = fmaxf(v.y, 0.f);
        v.z = fmaxf(v.z, 0.f); v.w = fmaxf(v.w, 0.f);
        out4[i] = v;
    }
}

// ---------------------------------------------------------------------------
extern "C" void kernel_launch(void* const* d_in, const int* in_sizes, int n_in,
                              void* d_out, int out_size)
{
    const float* h   = (const float*)d_in[0];   // (B,N,F)
    const int*   edge = (const int*)d_in[1];    // (B,E,2)
    const int*   edge_num = (const int*)d_in[2];// (B,)
    const float* ew  = (const float*)d_in[3];   // (B,E)
    const float* W   = (const float*)d_in[4];   // (F,F)
    const float* a   = (const float*)d_in[5];   // (1,2F)
    float* out = (float*)d_out;                 // (B,N,F)

    const int total4 = BB * NN * FF / 4;        // 1,048,576
    init_kernel<<<(total4 + 255) / 256, 256>>>((float4*)out);

    gemm_kernel<<<BB * NN / 32, 512>>>(h, W, a);

    edge_kernel<<<(BB * EE + 255) / 256, 256>>>(edge, edge_num, ew);

    scatter_kernel<<<(BB * EE * 16) / 256, 256>>>(edge, out);

    relu_kernel<<<(total4 + 255) / 256, 256>>>((float4*)out);
}

// round 6
// speedup vs baseline: 1.0051x; 1.0051x over previous
#include <cuda_runtime.h>

// Fixed problem shapes (from reference setup_inputs)
#define BB 4
#define NN 16384
#define EE 262144      // 2^18
#define FF 64
#define E_SHIFT 18

#define EXP_CLAMP 1000000.0f
#define DENOM_EPS 1e-10f
#define LRELU_ALPHA 0.01f

// Scratch (device globals; no allocation allowed)
__device__ float g_Wh[BB * NN * FF];     // 16.8 MB
__device__ float g_s1[BB * NN];
__device__ float g_s2[BB * NN];
__device__ float g_denom[BB * NN];
__device__ float g_xexp[BB * EE];

// ---------------------------------------------------------------------------
// Init: zero output, denom = eps
// ---------------------------------------------------------------------------
__global__ void init_kernel(float4* __restrict__ out4) {
    int i = blockIdx.x * blockDim.x + threadIdx.x;
    const int total4 = BB * NN * FF / 4;   // 1,048,576
    if (i < total4) out4[i] = make_float4(0.f, 0.f, 0.f, 0.f);
    if (i < BB * NN) g_denom[i] = DENOM_EPS;
}

// ---------------------------------------------------------------------------
// GEMM: Wh[b,n,o] = sum_f h[b,n,f] * W[o,f], fused s1/s2 epilogue.
// Block: 512 threads, 32 rows/block, 16 threads per row, 4 cols per thread.
// ---------------------------------------------------------------------------
__global__ __launch_bounds__(512) void gemm_kernel(
    const float* __restrict__ h,
    const float* __restrict__ W,
    const float* __restrict__ a)
{
    __shared__ __align__(16) float Wsh[64 * 68];  // [f][o] transposed, row pad 68
    __shared__ float hsh[32][65];                 // padded rows

    const int t = threadIdx.x;
    const int base = blockIdx.x * 32;             // row base within B*N

    // Load W transposed: Wsh[f*68 + o] = W[o*64 + f]
    // (strided global reads, conflict-free smem writes; W is tiny & L1/L2 hot)
    for (int i = t; i < 4096; i += 512) {
        int f = i >> 6, o = i & 63;
        Wsh[f * 68 + o] = W[o * 64 + f];
    }
    // Load 32 h rows (coalesced)
    for (int i = t; i < 2048; i += 512) {
        int r = i >> 6, f = i & 63;
        hsh[r][f] = h[(base + r) * 64 + f];
    }
    __syncthreads();

    const int r  = t >> 4;          // 0..31
    const int cg = (t & 15) << 2;   // 0,4,...,60

    float a0 = 0.f, a1 = 0.f, a2 = 0.f, a3 = 0.f;
#pragma unroll
    for (int f = 0; f < 64; f++) {
        float hv = hsh[r][f];
        float4 w = *(const float4*)&Wsh[f * 68 + cg];
        a0 += hv * w.x; a1 += hv * w.y; a2 += hv * w.z; a3 += hv * w.w;
    }

    const int row = base + r;
    *(float4*)&g_Wh[row * 64 + cg] = make_float4(a0, a1, a2, a3);

    // s1 = dot(Wh[row], a[0:64]), s2 = dot(Wh[row], a[64:128])
    float s1 = a0 * a[cg] + a1 * a[cg + 1] + a2 * a[cg + 2] + a3 * a[cg + 3];
    float s2 = a0 * a[64 + cg] + a1 * a[64 + cg + 1] + a2 * a[64 + cg + 2] + a3 * a[64 + cg + 3];
#pragma unroll
    for (int off = 8; off > 0; off >>= 1) {
        s1 += __shfl_down_sync(0xffffffffu, s1, off, 16);
        s2 += __shfl_down_sync(0xffffffffu, s2, off, 16);
    }
    if ((t & 15) == 0) {
        g_s1[row] = s1;
        g_s2[row] = s2;
    }
}

// ---------------------------------------------------------------------------
// Edge pass: x_exp + denom accumulation. One thread per (b,e).
// ---------------------------------------------------------------------------
__global__ void edge_kernel(
    const int* __restrict__ edge,
    const int* __restrict__ edge_num,
    const float* __restrict__ ew)
{
    int idx = blockIdx.x * blockDim.x + threadIdx.x;
    if (idx >= BB * EE) return;
    int b = idx >> E_SHIFT;
    int e = idx & (EE - 1);

    float x = 0.f;
    if (e < edge_num[b]) {
        int2 pr = ((const int2*)edge)[idx];     // {ctr, nbr}
        float z = ew[idx] * (g_s1[b * NN + pr.x] + g_s2[b * NN + pr.y]);
        z = (z > 0.f) ? z : LRELU_ALPHA * z;    // leaky relu
        x = fminf(__expf(z), EXP_CLAMP);        // clip(exp, 0, 1e6)
        atomicAdd(&g_denom[b * NN + pr.x], x);
    }
    g_xexp[idx] = x;
}

// ---------------------------------------------------------------------------
// Scatter: out[b, ctr, :] += (x/denom[ctr]) * Wh[b, nbr, :]
// 16 lanes per edge, 4 floats per lane (float4 gather + 4 scalar RED).
// ---------------------------------------------------------------------------
__global__ __launch_bounds__(256) void scatter_kernel(
    const int* __restrict__ edge,
    float* __restrict__ out)
{
    int gt = blockIdx.x * blockDim.x + threadIdx.x;
    int eidx = gt >> 4;
    if (eidx >= BB * EE) return;

    float x = g_xexp[eidx];
    if (x == 0.f) return;                       // masked or underflowed edge

    int lane = gt & 15;
    int b = eidx >> E_SHIFT;
    int2 pr = ((const int2*)edge)[eidx];        // {ctr, nbr}

    float att = x / g_denom[b * NN + pr.x];
    float4 wh = *(const float4*)&g_Wh[(b * NN + pr.y) * 64 + lane * 4];
    float* o = &out[(b * NN + pr.x) * 64 + lane * 4];
    atomicAdd(o + 0, att * wh.x);
    atomicAdd(o + 1, att * wh.y);
    atomicAdd(o + 2, att * wh.z);
    atomicAdd(o + 3, att * wh.w);
}

// ---------------------------------------------------------------------------
// Final relu
// ---------------------------------------------------------------------------
__global__ void relu_kernel(float4* __restrict__ out4) {
    int i = blockIdx.x * blockDim.x + threadIdx.x;
    const int total4 = BB * NN * FF / 4;
    if (i < total4) {
        float4 v = out4[i];
        v.x = fmaxf(v.x, 0.f); v.y = fmaxf(v.y, 0.f);
        v.z = fmaxf(v.z, 0.f); v.w = fmaxf(v.w, 0.f);
        out4[i] = v;
    }
}

// ---------------------------------------------------------------------------
extern "C" void kernel_launch(void* const* d_in, const int* in_sizes, int n_in,
                              void* d_out, int out_size)
{
    const float* h   = (const float*)d_in[0];   // (B,N,F)
    const int*   edge = (const int*)d_in[1];    // (B,E,2)
    const int*   edge_num = (const int*)d_in[2];// (B,)
    const float* ew  = (const float*)d_in[3];   // (B,E)
    const float* W   = (const float*)d_in[4];   // (F,F)
    const float* a   = (const float*)d_in[5];   // (1,2F)
    float* out = (float*)d_out;                 // (B,N,F)

    const int total4 = BB * NN * FF / 4;        // 1,048,576
    init_kernel<<<(total4 + 255) / 256, 256>>>((float4*)out);

    gemm_kernel<<<BB * NN / 32, 512>>>(h, W, a);

    edge_kernel<<<(BB * EE + 255) / 256, 256>>>(edge, edge_num, ew);

    scatter_kernel<<<(BB * EE * 16) / 256, 256>>>(edge, out);

    relu_kernel<<<(total4 + 255) / 256, 256>>>((float4*)out);
}

// round 7
// speedup vs baseline: 1.3096x; 1.3030x over previous
#include <cuda_runtime.h>

// Fixed problem shapes (from reference setup_inputs)
#define BB 4
#define NN 16384
#define EE 262144      // 2^18
#define FF 64
#define E_SHIFT 18

#define EXP_CLAMP 1000000.0f
#define DENOM_EPS 1e-10f
#define LRELU_ALPHA 0.01f

// Scratch (device globals; no allocation allowed)
__device__ float g_Wh[BB * NN * FF];     // 16.8 MB
__device__ float g_s1[BB * NN];
__device__ float g_s2[BB * NN];
__device__ float g_denom[BB * NN];
__device__ float g_xexp[BB * EE];

// ---------------------------------------------------------------------------
// Init: zero output, denom = eps
// ---------------------------------------------------------------------------
__global__ void init_kernel(float4* __restrict__ out4) {
    int i = blockIdx.x * blockDim.x + threadIdx.x;
    const int total4 = BB * NN * FF / 4;   // 1,048,576
    if (i < total4) out4[i] = make_float4(0.f, 0.f, 0.f, 0.f);
    if (i < BB * NN) g_denom[i] = DENOM_EPS;
}

// ---------------------------------------------------------------------------
// GEMM: Wh[b,n,o] = sum_f h[b,n,f] * W[o,f], fused s1/s2 epilogue.
// Block: 512 threads, 32 rows/block, 16 threads per row, 4 cols per thread.
// ---------------------------------------------------------------------------
__global__ __launch_bounds__(512) void gemm_kernel(
    const float* __restrict__ h,
    const float* __restrict__ W,
    const float* __restrict__ a)
{
    __shared__ __align__(16) float Wsh[64 * 68];  // [f][o] transposed, row pad 68
    __shared__ float hsh[32][65];                 // padded rows

    const int t = threadIdx.x;
    const int base = blockIdx.x * 32;             // row base within B*N

    // Load W transposed: Wsh[f*68 + o] = W[o*64 + f]
    for (int i = t; i < 4096; i += 512) {
        int f = i >> 6, o = i & 63;
        Wsh[f * 68 + o] = W[o * 64 + f];
    }
    // Load 32 h rows (coalesced)
    for (int i = t; i < 2048; i += 512) {
        int r = i >> 6, f = i & 63;
        hsh[r][f] = h[(base + r) * 64 + f];
    }
    __syncthreads();

    const int r  = t >> 4;          // 0..31
    const int cg = (t & 15) << 2;   // 0,4,...,60

    float a0 = 0.f, a1 = 0.f, a2 = 0.f, a3 = 0.f;
#pragma unroll
    for (int f = 0; f < 64; f++) {
        float hv = hsh[r][f];
        float4 w = *(const float4*)&Wsh[f * 68 + cg];
        a0 += hv * w.x; a1 += hv * w.y; a2 += hv * w.z; a3 += hv * w.w;
    }

    const int row = base + r;
    *(float4*)&g_Wh[row * 64 + cg] = make_float4(a0, a1, a2, a3);

    // s1 = dot(Wh[row], a[0:64]), s2 = dot(Wh[row], a[64:128])
    float s1 = a0 * a[cg] + a1 * a[cg + 1] + a2 * a[cg + 2] + a3 * a[cg + 3];
    float s2 = a0 * a[64 + cg] + a1 * a[64 + cg + 1] + a2 * a[64 + cg + 2] + a3 * a[64 + cg + 3];
#pragma unroll
    for (int off = 8; off > 0; off >>= 1) {
        s1 += __shfl_down_sync(0xffffffffu, s1, off, 16);
        s2 += __shfl_down_sync(0xffffffffu, s2, off, 16);
    }
    if ((t & 15) == 0) {
        g_s1[row] = s1;
        g_s2[row] = s2;
    }
}

// ---------------------------------------------------------------------------
// Edge pass: x_exp + denom accumulation. One thread per (b,e).
// ---------------------------------------------------------------------------
__global__ void edge_kernel(
    const int* __restrict__ edge,
    const int* __restrict__ edge_num,
    const float* __restrict__ ew)
{
    int idx = blockIdx.x * blockDim.x + threadIdx.x;
    if (idx >= BB * EE) return;
    int b = idx >> E_SHIFT;
    int e = idx & (EE - 1);

    float x = 0.f;
    if (e < edge_num[b]) {
        int2 pr = ((const int2*)edge)[idx];     // {ctr, nbr}
        float z = ew[idx] * (g_s1[b * NN + pr.x] + g_s2[b * NN + pr.y]);
        z = (z > 0.f) ? z : LRELU_ALPHA * z;    // leaky relu
        x = fminf(__expf(z), EXP_CLAMP);        // clip(exp, 0, 1e6)
        atomicAdd(&g_denom[b * NN + pr.x], x);
    }
    g_xexp[idx] = x;
}

// ---------------------------------------------------------------------------
// Scatter: out[b, ctr, :] += (x/denom[ctr]) * Wh[b, nbr, :]
// 16 lanes per edge, 1 float4 gather + 1 vector red.global.add.v4.f32 per lane.
// ---------------------------------------------------------------------------
__global__ __launch_bounds__(256) void scatter_kernel(
    const int* __restrict__ edge,
    float* __restrict__ out)
{
    int gt = blockIdx.x * blockDim.x + threadIdx.x;
    int eidx = gt >> 4;
    if (eidx >= BB * EE) return;

    float x = g_xexp[eidx];
    if (x == 0.f) return;                       // masked or underflowed edge

    int lane = gt & 15;
    int b = eidx >> E_SHIFT;
    int2 pr = ((const int2*)edge)[eidx];        // {ctr, nbr}

    float att = __fdividef(x, g_denom[b * NN + pr.x]);
    float4 wh = *(const float4*)&g_Wh[(b * NN + pr.y) * 64 + lane * 4];
    float* o = &out[(b * NN + pr.x) * 64 + lane * 4];

    asm volatile("red.global.add.v4.f32 [%0], {%1, %2, %3, %4};"
                 :: "l"(o),
                    "f"(att * wh.x), "f"(att * wh.y),
                    "f"(att * wh.z), "f"(att * wh.w)
                 : "memory");
}

// ---------------------------------------------------------------------------
// Final relu
// ---------------------------------------------------------------------------
__global__ void relu_kernel(float4* __restrict__ out4) {
    int i = blockIdx.x * blockDim.x + threadIdx.x;
    const int total4 = BB * NN * FF / 4;
    if (i < total4) {
        float4 v = out4[i];
        v.x = fmaxf(v.x, 0.f); v.y = fmaxf(v.y, 0.f);
        v.z = fmaxf(v.z, 0.f); v.w = fmaxf(v.w, 0.f);
        out4[i] = v;
    }
}

// ---------------------------------------------------------------------------
extern "C" void kernel_launch(void* const* d_in, const int* in_sizes, int n_in,
                              void* d_out, int out_size)
{
    const float* h   = (const float*)d_in[0];   // (B,N,F)
    const int*   edge = (const int*)d_in[1];    // (B,E,2)
    const int*   edge_num = (const int*)d_in[2];// (B,)
    const float* ew  = (const float*)d_in[3];   // (B,E)
    const float* W   = (const float*)d_in[4];   // (F,F)
    const float* a   = (const float*)d_in[5];   // (1,2F)
    float* out = (float*)d_out;                 // (B,N,F)

    const int total4 = BB * NN * FF / 4;        // 1,048,576
    init_kernel<<<(total4 + 255) / 256, 256>>>((float4*)out);

    gemm_kernel<<<BB * NN / 32, 512>>>(h, W, a);

    edge_kernel<<<(BB * EE + 255) / 256, 256>>>(edge, edge_num, ew);

    scatter_kernel<<<(BB * EE * 16) / 256, 256>>>(edge, out);

    relu_kernel<<<(total4 + 255) / 256, 256>>>((float4*)out);
}

// round 8
// speedup vs baseline: 1.3908x; 1.0620x over previous
#include <cuda_runtime.h>

// Fixed problem shapes (from reference setup_inputs)
#define BB 4
#define NN 16384
#define EE 262144      // 2^18
#define FF 64
#define E_SHIFT 18
#define NTOT (BB * NN)          // 65536 nodes total
#define ETOT (BB * EE)          // 1,048,576 edge slots

#define EXP_CLAMP 1000000.0f
#define DENOM_EPS 1e-10f
#define LRELU_ALPHA 0.01f

// Scratch (device globals; no allocation allowed)
__device__ float g_Wh[NTOT * FF];        // 16.8 MB
__device__ float g_s1[NTOT];
__device__ float g_s2[NTOT];
__device__ float g_xexp[ETOT];           // 4 MB
__device__ int   g_hist[NTOT];           // per-node active-edge count
__device__ int   g_scan[NTOT];           // block-local exclusive scan
__device__ int   g_bsum[64];             // per-scan-block sums
__device__ int   g_boff[64];             // scanned block sums
__device__ int   g_off[NTOT];            // segment start offsets
__device__ int   g_cursor[NTOT];         // rank cursors (reset every call)
__device__ int2  g_sorted[ETOT];         // {nbr_global, xexp bits} grouped by ctr

// ---------------------------------------------------------------------------
// Zero the histogram
// ---------------------------------------------------------------------------
__global__ void hist0_kernel() {
    int i = blockIdx.x * blockDim.x + threadIdx.x;
    if (i < NTOT) g_hist[i] = 0;
}

// ---------------------------------------------------------------------------
// GEMM: Wh[b,n,o] = sum_f h[b,n,f] * W[o,f], fused s1/s2 epilogue.
// ---------------------------------------------------------------------------
__global__ __launch_bounds__(512) void gemm_kernel(
    const float* __restrict__ h,
    const float* __restrict__ W,
    const float* __restrict__ a)
{
    __shared__ __align__(16) float Wsh[64 * 68];  // [f][o] transposed, row pad 68
    __shared__ float hsh[32][65];                 // padded rows

    const int t = threadIdx.x;
    const int base = blockIdx.x * 32;             // row base within B*N

    for (int i = t; i < 4096; i += 512) {
        int f = i >> 6, o = i & 63;
        Wsh[f * 68 + o] = W[o * 64 + f];
    }
    for (int i = t; i < 2048; i += 512) {
        int r = i >> 6, f = i & 63;
        hsh[r][f] = h[(base + r) * 64 + f];
    }
    __syncthreads();

    const int r  = t >> 4;          // 0..31
    const int cg = (t & 15) << 2;   // 0,4,...,60

    float a0 = 0.f, a1 = 0.f, a2 = 0.f, a3 = 0.f;
#pragma unroll
    for (int f = 0; f < 64; f++) {
        float hv = hsh[r][f];
        float4 w = *(const float4*)&Wsh[f * 68 + cg];
        a0 += hv * w.x; a1 += hv * w.y; a2 += hv * w.z; a3 += hv * w.w;
    }

    const int row = base + r;
    *(float4*)&g_Wh[row * 64 + cg] = make_float4(a0, a1, a2, a3);

    float s1 = a0 * a[cg] + a1 * a[cg + 1] + a2 * a[cg + 2] + a3 * a[cg + 3];
    float s2 = a0 * a[64 + cg] + a1 * a[64 + cg + 1] + a2 * a[64 + cg + 2] + a3 * a[64 + cg + 3];
#pragma unroll
    for (int off = 8; off > 0; off >>= 1) {
        s1 += __shfl_down_sync(0xffffffffu, s1, off, 16);
        s2 += __shfl_down_sync(0xffffffffu, s2, off, 16);
    }
    if ((t & 15) == 0) {
        g_s1[row] = s1;
        g_s2[row] = s2;
    }
}

// ---------------------------------------------------------------------------
// Edge pass: x_exp + ctr histogram. One thread per (b,e). No float atomics.
// ---------------------------------------------------------------------------
__global__ void edge_kernel(
    const int* __restrict__ edge,
    const int* __restrict__ edge_num,
    const float* __restrict__ ew)
{
    int idx = blockIdx.x * blockDim.x + threadIdx.x;
    if (idx >= ETOT) return;
    int b = idx >> E_SHIFT;
    int e = idx & (EE - 1);

    if (e < edge_num[b]) {
        int2 pr = ((const int2*)edge)[idx];     // {ctr, nbr}
        float z = ew[idx] * (g_s1[b * NN + pr.x] + g_s2[b * NN + pr.y]);
        z = (z > 0.f) ? z : LRELU_ALPHA * z;    // leaky relu
        float x = fminf(__expf(z), EXP_CLAMP);  // clip(exp, 0, 1e6)
        g_xexp[idx] = x;
        atomicAdd(&g_hist[b * NN + pr.x], 1);
    }
}

// ---------------------------------------------------------------------------
// Prefix scan of g_hist (65536 = 64 blocks x 1024)
// ---------------------------------------------------------------------------
__global__ __launch_bounds__(1024) void scan1_kernel() {
    __shared__ int wsums[32];
    int i = blockIdx.x * 1024 + threadIdx.x;
    int v = g_hist[i];
    int lane = threadIdx.x & 31, w = threadIdx.x >> 5;

    int inc = v;
#pragma unroll
    for (int off = 1; off < 32; off <<= 1) {
        int n = __shfl_up_sync(0xffffffffu, inc, off);
        if (lane >= off) inc += n;
    }
    if (lane == 31) wsums[w] = inc;
    __syncthreads();
    if (w == 0) {
        int s = wsums[lane];
#pragma unroll
        for (int off = 1; off < 32; off <<= 1) {
            int n = __shfl_up_sync(0xffffffffu, s, off);
            if (lane >= off) s += n;
        }
        wsums[lane] = s;
    }
    __syncthreads();
    int excl = inc - v + (w > 0 ? wsums[w - 1] : 0);
    g_scan[i] = excl;
    if (threadIdx.x == 1023) g_bsum[blockIdx.x] = excl + v;
}

__global__ void scan2_kernel() {
    if (threadIdx.x == 0 && blockIdx.x == 0) {
        int s = 0;
        for (int i = 0; i < 64; i++) { int t = g_bsum[i]; g_boff[i] = s; s += t; }
    }
}

__global__ __launch_bounds__(1024) void scan3_kernel() {
    int i = blockIdx.x * 1024 + threadIdx.x;
    int off = g_scan[i] + g_boff[blockIdx.x];
    g_off[i] = off;
    g_cursor[i] = off;
}

// ---------------------------------------------------------------------------
// Reorder: group active edges by ctr node.  slot = cursor[ctr]++
// ---------------------------------------------------------------------------
__global__ void reorder_kernel(
    const int* __restrict__ edge,
    const int* __restrict__ edge_num)
{
    int idx = blockIdx.x * blockDim.x + threadIdx.x;
    if (idx >= ETOT) return;
    int b = idx >> E_SHIFT;
    int e = idx & (EE - 1);
    if (e >= edge_num[b]) return;

    int2 pr = ((const int2*)edge)[idx];         // {ctr, nbr}
    int slot = atomicAdd(&g_cursor[b * NN + pr.x], 1);
    g_sorted[slot] = make_int2(b * NN + pr.y, __float_as_int(g_xexp[idx]));
}

// ---------------------------------------------------------------------------
// Gather: per node, acc = sum x*Wh[nbr], dsum = sum x; out = relu(acc/(eps+dsum))
// 64 threads per node (one feature each), 4 nodes per 256-thread block.
// No atomics; writes every output element exactly once (relu fused).
// ---------------------------------------------------------------------------
__global__ __launch_bounds__(256) void gather_kernel(float* __restrict__ out) {
    int node = blockIdx.x * 4 + (threadIdx.x >> 6);
    int f = threadIdx.x & 63;
    int start = g_off[node];
    int cnt = g_hist[node];

    float acc = 0.f, dsum = 0.f;
#pragma unroll 4
    for (int j = 0; j < cnt; j++) {
        int2 ex = g_sorted[start + j];
        float x = __int_as_float(ex.y);
        dsum += x;
        acc += x * g_Wh[ex.x * 64 + f];
    }
    float v = acc * __frcp_rn(DENOM_EPS + dsum);
    out[node * 64 + f] = fmaxf(v, 0.f);
}

// ---------------------------------------------------------------------------
extern "C" void kernel_launch(void* const* d_in, const int* in_sizes, int n_in,
                              void* d_out, int out_size)
{
    const float* h   = (const float*)d_in[0];   // (B,N,F)
    const int*   edge = (const int*)d_in[1];    // (B,E,2)
    const int*   edge_num = (const int*)d_in[2];// (B,)
    const float* ew  = (const float*)d_in[3];   // (B,E)
    const float* W   = (const float*)d_in[4];   // (F,F)
    const float* a   = (const float*)d_in[5];   // (1,2F)
    float* out = (float*)d_out;                 // (B,N,F)

    hist0_kernel<<<NTOT / 256, 256>>>();

    gemm_kernel<<<NTOT / 32, 512>>>(h, W, a);

    edge_kernel<<<ETOT / 256, 256>>>(edge, edge_num, ew);

    scan1_kernel<<<64, 1024>>>();
    scan2_kernel<<<1, 32>>>();
    scan3_kernel<<<64, 1024>>>();

    reorder_kernel<<<ETOT / 256, 256>>>(edge, edge_num);

    gather_kernel<<<NTOT / 4, 256>>>(out);
}

// round 9
// speedup vs baseline: 2.1696x; 1.5599x over previous
#include <cuda_runtime.h>

// Fixed problem shapes (from reference setup_inputs)
#define BB 4
#define NN 16384
#define EE 262144      // 2^18
#define FF 64
#define E_SHIFT 18
#define NTOT (BB * NN)          // 65536 nodes total
#define ETOT (BB * EE)          // 1,048,576 edge slots

#define EXP_CLAMP 1000000.0f
#define DENOM_EPS 1e-10f
#define LRELU_ALPHA 0.01f

// Scratch (device globals; zero-initialized at load; no allocation allowed)
__device__ float g_Wh[NTOT * FF];        // 16.8 MB
__device__ float g_s1[NTOT];
__device__ float g_s2[NTOT];
__device__ float g_xexp[ETOT];           // 4 MB
__device__ int   g_rank[ETOT];           // 4 MB: rank of edge within its ctr segment
__device__ int   g_hist[NTOT];           // per-node active-edge count (self-cleared by gather)
__device__ int   g_scan[NTOT];           // block-local exclusive scan
__device__ int   g_bsum[64];             // per-scan-block sums
__device__ int   g_boff[64];             // scanned block sums
__device__ int2  g_sorted[ETOT];         // {nbr_global, xexp bits} grouped by ctr

// ---------------------------------------------------------------------------
// GEMM: Wh[b,n,o] = sum_f h[b,n,f] * W[o,f], fused s1/s2 epilogue.
// 64x64 tile per 256-thread block, 4x4 register tile per thread.
// Per k-step: 2 LDS.128 (both broadcast-friendly) feed 16 FFMA.
// ---------------------------------------------------------------------------
__global__ __launch_bounds__(256) void gemm_kernel(
    const float* __restrict__ h,
    const float* __restrict__ W,
    const float* __restrict__ a)
{
    __shared__ __align__(16) float Wsh[64 * 68];   // [k][o], pad 68 (16B aligned rows)
    __shared__ __align__(16) float hshT[64 * 68];  // [k][r] transposed h tile

    const int t = threadIdx.x;
    const int base = blockIdx.x * 64;              // row base within B*N

    // Load W transposed: Wsh[k*68+o] = W[o*64+k] (coalesced reads)
    for (int i = t; i < 4096; i += 256) {
        int o = i >> 6, k = i & 63;
        Wsh[k * 68 + o] = W[i];
    }
    // Load 64 h rows transposed: hshT[k*68+r] = h[(base+r)*64+k] (coalesced reads)
    for (int i = t; i < 4096; i += 256) {
        int r = i >> 6, k = i & 63;
        hshT[k * 68 + r] = h[base * 64 + i];
    }
    __syncthreads();

    const int tx = t & 15, ty = t >> 4;
    const int r0 = ty * 4, c0 = tx * 4;

    float acc[4][4];
#pragma unroll
    for (int i = 0; i < 4; i++)
#pragma unroll
        for (int j = 0; j < 4; j++) acc[i][j] = 0.f;

#pragma unroll
    for (int k = 0; k < 64; k++) {
        float4 av = *(const float4*)&hshT[k * 68 + r0];
        float4 bv = *(const float4*)&Wsh[k * 68 + c0];
        acc[0][0] += av.x * bv.x; acc[0][1] += av.x * bv.y; acc[0][2] += av.x * bv.z; acc[0][3] += av.x * bv.w;
        acc[1][0] += av.y * bv.x; acc[1][1] += av.y * bv.y; acc[1][2] += av.y * bv.z; acc[1][3] += av.y * bv.w;
        acc[2][0] += av.z * bv.x; acc[2][1] += av.z * bv.y; acc[2][2] += av.z * bv.z; acc[2][3] += av.z * bv.w;
        acc[3][0] += av.w * bv.x; acc[3][1] += av.w * bv.y; acc[3][2] += av.w * bv.z; acc[3][3] += av.w * bv.w;
    }

    const float4 a1 = *(const float4*)&a[c0];
    const float4 a2 = *(const float4*)&a[64 + c0];

    float s1v[4], s2v[4];
#pragma unroll
    for (int i = 0; i < 4; i++) {
        int row = base + r0 + i;
        *(float4*)&g_Wh[row * 64 + c0] =
            make_float4(acc[i][0], acc[i][1], acc[i][2], acc[i][3]);
        s1v[i] = acc[i][0] * a1.x + acc[i][1] * a1.y + acc[i][2] * a1.z + acc[i][3] * a1.w;
        s2v[i] = acc[i][0] * a2.x + acc[i][1] * a2.y + acc[i][2] * a2.z + acc[i][3] * a2.w;
    }
#pragma unroll
    for (int off = 8; off > 0; off >>= 1) {
#pragma unroll
        for (int i = 0; i < 4; i++) {
            s1v[i] += __shfl_down_sync(0xffffffffu, s1v[i], off, 16);
            s2v[i] += __shfl_down_sync(0xffffffffu, s2v[i], off, 16);
        }
    }
    if (tx == 0) {
#pragma unroll
        for (int i = 0; i < 4; i++) {
            g_s1[base + r0 + i] = s1v[i];
            g_s2[base + r0 + i] = s2v[i];
        }
    }
}

// ---------------------------------------------------------------------------
// Edge pass: x_exp + ctr histogram; the atomic's return value IS the edge's
// rank within its segment — persist it so reorder needs no atomics.
// ---------------------------------------------------------------------------
__global__ void edge_kernel(
    const int* __restrict__ edge,
    const int* __restrict__ edge_num,
    const float* __restrict__ ew)
{
    int idx = blockIdx.x * blockDim.x + threadIdx.x;
    if (idx >= ETOT) return;
    int b = idx >> E_SHIFT;
    int e = idx & (EE - 1);

    if (e < edge_num[b]) {
        int2 pr = ((const int2*)edge)[idx];     // {ctr, nbr}
        float z = ew[idx] * (g_s1[b * NN + pr.x] + g_s2[b * NN + pr.y]);
        z = (z > 0.f) ? z : LRELU_ALPHA * z;    // leaky relu
        float x = fminf(__expf(z), EXP_CLAMP);  // clip(exp, 0, 1e6)
        g_xexp[idx] = x;
        g_rank[idx] = atomicAdd(&g_hist[b * NN + pr.x], 1);
    }
}

// ---------------------------------------------------------------------------
// Prefix scan of g_hist (65536 = 64 blocks x 1024)
// ---------------------------------------------------------------------------
__global__ __launch_bounds__(1024) void scan1_kernel() {
    __shared__ int wsums[32];
    int i = blockIdx.x * 1024 + threadIdx.x;
    int v = g_hist[i];
    int lane = threadIdx.x & 31, w = threadIdx.x >> 5;

    int inc = v;
#pragma unroll
    for (int off = 1; off < 32; off <<= 1) {
        int n = __shfl_up_sync(0xffffffffu, inc, off);
        if (lane >= off) inc += n;
    }
    if (lane == 31) wsums[w] = inc;
    __syncthreads();
    if (w == 0) {
        int s = wsums[lane];
#pragma unroll
        for (int off = 1; off < 32; off <<= 1) {
            int n = __shfl_up_sync(0xffffffffu, s, off);
            if (lane >= off) s += n;
        }
        wsums[lane] = s;
    }
    __syncthreads();
    int excl = inc - v + (w > 0 ? wsums[w - 1] : 0);
    g_scan[i] = excl;
    if (threadIdx.x == 1023) g_bsum[blockIdx.x] = excl + v;
}

__global__ void scan2_kernel() {
    if (threadIdx.x == 0) {
        int s = 0;
        for (int i = 0; i < 64; i++) { int t = g_bsum[i]; g_boff[i] = s; s += t; }
    }
}

// ---------------------------------------------------------------------------
// Reorder: slot = scan[ctr] + boff[ctr>>10] + rank.  No atomics.
// ---------------------------------------------------------------------------
__global__ void reorder_kernel(
    const int* __restrict__ edge,
    const int* __restrict__ edge_num)
{
    int idx = blockIdx.x * blockDim.x + threadIdx.x;
    if (idx >= ETOT) return;
    int b = idx >> E_SHIFT;
    int e = idx & (EE - 1);
    if (e >= edge_num[b]) return;

    int2 pr = ((const int2*)edge)[idx];         // {ctr, nbr}
    int gc = b * NN + pr.x;
    int slot = g_scan[gc] + g_boff[gc >> 10] + g_rank[idx];
    g_sorted[slot] = make_int2(b * NN + pr.y, __float_as_int(g_xexp[idx]));
}

// ---------------------------------------------------------------------------
// Gather: per node, acc = sum x*Wh[nbr], dsum = sum x; out = relu(acc/(eps+dsum))
// 64 threads per node (one feature each). No atomics; one write per element.
// Self-clears g_hist for the next graph replay.
// ---------------------------------------------------------------------------
__global__ __launch_bounds__(256) void gather_kernel(float* __restrict__ out) {
    int node = blockIdx.x * 4 + (threadIdx.x >> 6);
    int f = threadIdx.x & 63;
    int start = g_scan[node] + g_boff[node >> 10];
    int cnt = g_hist[node];

    float acc = 0.f, dsum = 0.f;
#pragma unroll 4
    for (int j = 0; j < cnt; j++) {
        int2 ex = g_sorted[start + j];
        float x = __int_as_float(ex.y);
        dsum += x;
        acc += x * g_Wh[ex.x * 64 + f];
    }
    float v = acc * __frcp_rn(DENOM_EPS + dsum);
    out[node * 64 + f] = fmaxf(v, 0.f);
    if (f == 0) g_hist[node] = 0;   // reset for next call (zero-init invariant)
}

// ---------------------------------------------------------------------------
extern "C" void kernel_launch(void* const* d_in, const int* in_sizes, int n_in,
                              void* d_out, int out_size)
{
    const float* h   = (const float*)d_in[0];   // (B,N,F)
    const int*   edge = (const int*)d_in[1];    // (B,E,2)
    const int*   edge_num = (const int*)d_in[2];// (B,)
    const float* ew  = (const float*)d_in[3];   // (B,E)
    const float* W   = (const float*)d_in[4];   // (F,F)
    const float* a   = (const float*)d_in[5];   // (1,2F)
    float* out = (float*)d_out;                 // (B,N,F)

    gemm_kernel<<<NTOT / 64, 256>>>(h, W, a);

    edge_kernel<<<ETOT / 256, 256>>>(edge, edge_num, ew);

    scan1_kernel<<<64, 1024>>>();
    scan2_kernel<<<1, 32>>>();

    reorder_kernel<<<ETOT / 256, 256>>>(edge, edge_num);

    gather_kernel<<<NTOT / 4, 256>>>(out);
}

// round 10
// speedup vs baseline: 2.1720x; 1.0011x over previous
#include <cuda_runtime.h>

// Fixed problem shapes (from reference setup_inputs)
#define BB 4
#define NN 16384
#define EE 262144      // 2^18
#define FF 64
#define E_SHIFT 18
#define NTOT (BB * NN)          // 65536 nodes total
#define ETOT (BB * EE)          // 1,048,576 edge slots

#define EXP_CLAMP 1000000.0f
#define DENOM_EPS 1e-10f
#define LRELU_ALPHA 0.01f

// Scratch (device globals; zero-initialized at load; no allocation allowed)
__device__ float g_Wh[NTOT * FF];        // 16.8 MB
__device__ float g_s1[NTOT];
__device__ float g_s2[NTOT];
__device__ float g_xexp[ETOT];           // 4 MB
__device__ int   g_rank[ETOT];           // 4 MB: rank of edge within its ctr segment
__device__ int   g_hist[NTOT];           // per-node active-edge count (self-cleared by gather)
__device__ int   g_scan[NTOT];           // block-local exclusive scan
__device__ int   g_bsum[64];             // per-scan-block sums
__device__ int2  g_sorted[ETOT];         // {nbr_global, xexp bits} grouped by ctr

// Inline 64-wide exclusive scan of g_bsum into sboff[64] (warp 0 only; caller
// must __syncthreads() after). g_bsum is 256B, L2-resident → ~200 cyc.
__device__ __forceinline__ void scan_bsum_inline(int* sboff, int tid) {
    if (tid < 32) {
        int v0 = g_bsum[tid], v1 = g_bsum[32 + tid];
        int i0 = v0, i1 = v1;
#pragma unroll
        for (int off = 1; off < 32; off <<= 1) {
            int n0 = __shfl_up_sync(0xffffffffu, i0, off);
            int n1 = __shfl_up_sync(0xffffffffu, i1, off);
            if (tid >= off) { i0 += n0; i1 += n1; }
        }
        int tot0 = __shfl_sync(0xffffffffu, i0, 31);
        sboff[tid]      = i0 - v0;
        sboff[32 + tid] = i1 - v1 + tot0;
    }
}

// ---------------------------------------------------------------------------
// GEMM: Wh[b,n,o] = sum_f h[b,n,f] * W[o,f], fused s1/s2 epilogue.
// 64x64 tile per 256-thread block, 4x4 register tile per thread.
// ---------------------------------------------------------------------------
__global__ __launch_bounds__(256) void gemm_kernel(
    const float* __restrict__ h,
    const float* __restrict__ W,
    const float* __restrict__ a)
{
    __shared__ __align__(16) float Wsh[64 * 68];   // [k][o], pad 68
    __shared__ __align__(16) float hshT[64 * 68];  // [k][r] transposed h tile

    const int t = threadIdx.x;
    const int base = blockIdx.x * 64;              // row base within B*N

    for (int i = t; i < 4096; i += 256) {
        int o = i >> 6, k = i & 63;
        Wsh[k * 68 + o] = W[i];
    }
    for (int i = t; i < 4096; i += 256) {
        int r = i >> 6, k = i & 63;
        hshT[k * 68 + r] = h[base * 64 + i];
    }
    __syncthreads();

    const int tx = t & 15, ty = t >> 4;
    const int r0 = ty * 4, c0 = tx * 4;

    float acc[4][4];
#pragma unroll
    for (int i = 0; i < 4; i++)
#pragma unroll
        for (int j = 0; j < 4; j++) acc[i][j] = 0.f;

#pragma unroll
    for (int k = 0; k < 64; k++) {
        float4 av = *(const float4*)&hshT[k * 68 + r0];
        float4 bv = *(const float4*)&Wsh[k * 68 + c0];
        acc[0][0] += av.x * bv.x; acc[0][1] += av.x * bv.y; acc[0][2] += av.x * bv.z; acc[0][3] += av.x * bv.w;
        acc[1][0] += av.y * bv.x; acc[1][1] += av.y * bv.y; acc[1][2] += av.y * bv.z; acc[1][3] += av.y * bv.w;
        acc[2][0] += av.z * bv.x; acc[2][1] += av.z * bv.y; acc[2][2] += av.z * bv.z; acc[2][3] += av.z * bv.w;
        acc[3][0] += av.w * bv.x; acc[3][1] += av.w * bv.y; acc[3][2] += av.w * bv.z; acc[3][3] += av.w * bv.w;
    }

    const float4 a1 = *(const float4*)&a[c0];
    const float4 a2 = *(const float4*)&a[64 + c0];

    float s1v[4], s2v[4];
#pragma unroll
    for (int i = 0; i < 4; i++) {
        int row = base + r0 + i;
        *(float4*)&g_Wh[row * 64 + c0] =
            make_float4(acc[i][0], acc[i][1], acc[i][2], acc[i][3]);
        s1v[i] = acc[i][0] * a1.x + acc[i][1] * a1.y + acc[i][2] * a1.z + acc[i][3] * a1.w;
        s2v[i] = acc[i][0] * a2.x + acc[i][1] * a2.y + acc[i][2] * a2.z + acc[i][3] * a2.w;
    }
#pragma unroll
    for (int off = 8; off > 0; off >>= 1) {
#pragma unroll
        for (int i = 0; i < 4; i++) {
            s1v[i] += __shfl_down_sync(0xffffffffu, s1v[i], off, 16);
            s2v[i] += __shfl_down_sync(0xffffffffu, s2v[i], off, 16);
        }
    }
    if (tx == 0) {
#pragma unroll
        for (int i = 0; i < 4; i++) {
            g_s1[base + r0 + i] = s1v[i];
            g_s2[base + r0 + i] = s2v[i];
        }
    }
}

// ---------------------------------------------------------------------------
// Edge pass: x_exp + ctr histogram; atomic's return value = rank in segment.
// ---------------------------------------------------------------------------
__global__ void edge_kernel(
    const int* __restrict__ edge,
    const int* __restrict__ edge_num,
    const float* __restrict__ ew)
{
    int idx = blockIdx.x * blockDim.x + threadIdx.x;
    if (idx >= ETOT) return;
    int b = idx >> E_SHIFT;
    int e = idx & (EE - 1);

    if (e < edge_num[b]) {
        int2 pr = ((const int2*)edge)[idx];     // {ctr, nbr}
        float z = ew[idx] * (g_s1[b * NN + pr.x] + g_s2[b * NN + pr.y]);
        z = (z > 0.f) ? z : LRELU_ALPHA * z;    // leaky relu
        float x = fminf(__expf(z), EXP_CLAMP);  // clip(exp, 0, 1e6)
        g_xexp[idx] = x;
        g_rank[idx] = atomicAdd(&g_hist[b * NN + pr.x], 1);
    }
}

// ---------------------------------------------------------------------------
// Prefix scan of g_hist (65536 = 64 blocks x 1024); emits block sums.
// ---------------------------------------------------------------------------
__global__ __launch_bounds__(1024) void scan1_kernel() {
    __shared__ int wsums[32];
    int i = blockIdx.x * 1024 + threadIdx.x;
    int v = g_hist[i];
    int lane = threadIdx.x & 31, w = threadIdx.x >> 5;

    int inc = v;
#pragma unroll
    for (int off = 1; off < 32; off <<= 1) {
        int n = __shfl_up_sync(0xffffffffu, inc, off);
        if (lane >= off) inc += n;
    }
    if (lane == 31) wsums[w] = inc;
    __syncthreads();
    if (w == 0) {
        int s = wsums[lane];
#pragma unroll
        for (int off = 1; off < 32; off <<= 1) {
            int n = __shfl_up_sync(0xffffffffu, s, off);
            if (lane >= off) s += n;
        }
        wsums[lane] = s;
    }
    __syncthreads();
    int excl = inc - v + (w > 0 ? wsums[w - 1] : 0);
    g_scan[i] = excl;
    if (threadIdx.x == 1023) g_bsum[blockIdx.x] = excl + v;
}

// ---------------------------------------------------------------------------
// Reorder: slot = scan[ctr] + boff[ctr>>10] + rank. No atomics.
// boff computed inline from g_bsum (64 ints, L2-hot) — no scan2 kernel.
// ---------------------------------------------------------------------------
__global__ __launch_bounds__(256) void reorder_kernel(
    const int* __restrict__ edge,
    const int* __restrict__ edge_num)
{
    __shared__ int sboff[64];
    scan_bsum_inline(sboff, threadIdx.x);
    __syncthreads();

    int idx = blockIdx.x * blockDim.x + threadIdx.x;
    int b = idx >> E_SHIFT;
    int e = idx & (EE - 1);
    if (e >= edge_num[b]) return;

    int2 pr = ((const int2*)edge)[idx];         // {ctr, nbr}
    int gc = b * NN + pr.x;
    int slot = g_scan[gc] + sboff[gc >> 10] + g_rank[idx];
    g_sorted[slot] = make_int2(b * NN + pr.y, __float_as_int(g_xexp[idx]));
}

// ---------------------------------------------------------------------------
// Gather: per node, acc = sum x*Wh[nbr], dsum = sum x; out = relu(acc/(eps+dsum))
// 64 threads per node. No atomics; one write per element; relu fused.
// Self-clears g_hist for the next graph replay.
// ---------------------------------------------------------------------------
__global__ __launch_bounds__(256) void gather_kernel(float* __restrict__ out) {
    __shared__ int sboff[64];
    scan_bsum_inline(sboff, threadIdx.x);
    __syncthreads();

    int node = blockIdx.x * 4 + (threadIdx.x >> 6);
    int f = threadIdx.x & 63;
    int start = g_scan[node] + sboff[node >> 10];
    int cnt = g_hist[node];

    float acc = 0.f, dsum = 0.f;
#pragma unroll 4
    for (int j = 0; j < cnt; j++) {
        int2 ex = g_sorted[start + j];
        float x = __int_as_float(ex.y);
        dsum += x;
        acc += x * g_Wh[ex.x * 64 + f];
    }
    float v = acc * __frcp_rn(DENOM_EPS + dsum);
    out[node * 64 + f] = fmaxf(v, 0.f);
    if (f == 0) g_hist[node] = 0;   // reset for next call (zero-init invariant)
}

// ---------------------------------------------------------------------------
extern "C" void kernel_launch(void* const* d_in, const int* in_sizes, int n_in,
                              void* d_out, int out_size)
{
    const float* h   = (const float*)d_in[0];   // (B,N,F)
    const int*   edge = (const int*)d_in[1];    // (B,E,2)
    const int*   edge_num = (const int*)d_in[2];// (B,)
    const float* ew  = (const float*)d_in[3];   // (B,E)
    const float* W   = (const float*)d_in[4];   // (F,F)
    const float* a   = (const float*)d_in[5];   // (1,2F)
    float* out = (float*)d_out;                 // (B,N,F)

    gemm_kernel<<<NTOT / 64, 256>>>(h, W, a);

    edge_kernel<<<ETOT / 256, 256>>>(edge, edge_num, ew);

    scan1_kernel<<<64, 1024>>>();

    reorder_kernel<<<ETOT / 256, 256>>>(edge, edge_num);

    gather_kernel<<<NTOT / 4, 256>>>(out);
}

// round 11
// speedup vs baseline: 2.4587x; 1.1320x over previous
#include <cuda_runtime.h>

// Fixed problem shapes (from reference setup_inputs)
#define BB 4
#define NN 16384
#define EE 262144      // 2^18
#define FF 64
#define E_SHIFT 18
#define NTOT (BB * NN)          // 65536 nodes total
#define ETOT (BB * EE)          // 1,048,576 edge slots

#define EXP_CLAMP 1000000.0f
#define DENOM_EPS 1e-10f
#define LRELU_ALPHA 0.01f

// Scratch (device globals; zero-initialized at load; no allocation allowed)
__device__ float g_Wh[NTOT * FF];        // 16.8 MB
__device__ float g_s1[NTOT];
__device__ float g_s2[NTOT];
__device__ float g_xexp[ETOT];           // 4 MB
__device__ int   g_rank[ETOT];           // 4 MB: rank of edge within its ctr segment
__device__ int   g_hist[NTOT];           // per-node active-edge count (self-cleared by gather)
__device__ int   g_scan[NTOT];           // block-local exclusive scan (256-wide blocks)
__device__ int   g_bsum[256];            // per-scan-block sums
__device__ int2  g_sorted[ETOT];         // {nbr_global, xexp bits} grouped by ctr

// Inline 256-wide exclusive scan of g_bsum into sboff[256] (warp 0 only;
// caller must __syncthreads() after). g_bsum is 1KB, L2-resident.
__device__ __forceinline__ void scan_bsum_inline(int* sboff, int tid) {
    if (tid < 32) {
        int4 v0 = ((const int4*)g_bsum)[tid * 2];
        int4 v1 = ((const int4*)g_bsum)[tid * 2 + 1];
        int s = v0.x + v0.y + v0.z + v0.w + v1.x + v1.y + v1.z + v1.w;
        int inc = s;
#pragma unroll
        for (int off = 1; off < 32; off <<= 1) {
            int n = __shfl_up_sync(0xffffffffu, inc, off);
            if (tid >= off) inc += n;
        }
        int excl = inc - s;
        int base = tid * 8;
        sboff[base + 0] = excl; excl += v0.x;
        sboff[base + 1] = excl; excl += v0.y;
        sboff[base + 2] = excl; excl += v0.z;
        sboff[base + 3] = excl; excl += v0.w;
        sboff[base + 4] = excl; excl += v1.x;
        sboff[base + 5] = excl; excl += v1.y;
        sboff[base + 6] = excl; excl += v1.z;
        sboff[base + 7] = excl;
    }
}

// ---------------------------------------------------------------------------
// GEMM: Wh[b,n,o] = sum_f h[b,n,f] * W[o,f], fused s1/s2 epilogue.
// 64x64 tile per 256-thread block, 4x4 register tile per thread.
// ---------------------------------------------------------------------------
__global__ __launch_bounds__(256) void gemm_kernel(
    const float* __restrict__ h,
    const float* __restrict__ W,
    const float* __restrict__ a)
{
    __shared__ __align__(16) float Wsh[64 * 68];   // [k][o], pad 68
    __shared__ __align__(16) float hshT[64 * 68];  // [k][r] transposed h tile

    const int t = threadIdx.x;
    const int base = blockIdx.x * 64;              // row base within B*N

    for (int i = t; i < 4096; i += 256) {
        int o = i >> 6, k = i & 63;
        Wsh[k * 68 + o] = W[i];
    }
    for (int i = t; i < 4096; i += 256) {
        int r = i >> 6, k = i & 63;
        hshT[k * 68 + r] = h[base * 64 + i];
    }
    __syncthreads();

    const int tx = t & 15, ty = t >> 4;
    const int r0 = ty * 4, c0 = tx * 4;

    float acc[4][4];
#pragma unroll
    for (int i = 0; i < 4; i++)
#pragma unroll
        for (int j = 0; j < 4; j++) acc[i][j] = 0.f;

#pragma unroll
    for (int k = 0; k < 64; k++) {
        float4 av = *(const float4*)&hshT[k * 68 + r0];
        float4 bv = *(const float4*)&Wsh[k * 68 + c0];
        acc[0][0] += av.x * bv.x; acc[0][1] += av.x * bv.y; acc[0][2] += av.x * bv.z; acc[0][3] += av.x * bv.w;
        acc[1][0] += av.y * bv.x; acc[1][1] += av.y * bv.y; acc[1][2] += av.y * bv.z; acc[1][3] += av.y * bv.w;
        acc[2][0] += av.z * bv.x; acc[2][1] += av.z * bv.y; acc[2][2] += av.z * bv.z; acc[2][3] += av.z * bv.w;
        acc[3][0] += av.w * bv.x; acc[3][1] += av.w * bv.y; acc[3][2] += av.w * bv.z; acc[3][3] += av.w * bv.w;
    }

    const float4 a1 = *(const float4*)&a[c0];
    const float4 a2 = *(const float4*)&a[64 + c0];

    float s1v[4], s2v[4];
#pragma unroll
    for (int i = 0; i < 4; i++) {
        int row = base + r0 + i;
        *(float4*)&g_Wh[row * 64 + c0] =
            make_float4(acc[i][0], acc[i][1], acc[i][2], acc[i][3]);
        s1v[i] = acc[i][0] * a1.x + acc[i][1] * a1.y + acc[i][2] * a1.z + acc[i][3] * a1.w;
        s2v[i] = acc[i][0] * a2.x + acc[i][1] * a2.y + acc[i][2] * a2.z + acc[i][3] * a2.w;
    }
#pragma unroll
    for (int off = 8; off > 0; off >>= 1) {
#pragma unroll
        for (int i = 0; i < 4; i++) {
            s1v[i] += __shfl_down_sync(0xffffffffu, s1v[i], off, 16);
            s2v[i] += __shfl_down_sync(0xffffffffu, s2v[i], off, 16);
        }
    }
    if (tx == 0) {
#pragma unroll
        for (int i = 0; i < 4; i++) {
            g_s1[base + r0 + i] = s1v[i];
            g_s2[base + r0 + i] = s2v[i];
        }
    }
}

// ---------------------------------------------------------------------------
// Edge pass: 2 edges per thread (int4/float2 loads). x_exp + ctr histogram;
// atomic's return value = rank in segment.
// ---------------------------------------------------------------------------
__global__ __launch_bounds__(256) void edge_kernel(
    const int* __restrict__ edge,
    const int* __restrict__ edge_num,
    const float* __restrict__ ew)
{
    int p = blockIdx.x * blockDim.x + threadIdx.x;   // pair index
    int idx = p * 2;                                  // EE even -> pair never crosses b
    int b = idx >> E_SHIFT;
    int e = idx & (EE - 1);
    int en = edge_num[b];
    if (e >= en) return;                              // both inactive

    int4 pq = ((const int4*)edge)[p];                 // edge idx: {x,y}, idx+1: {z,w}
    float2 w2 = ((const float2*)ew)[p];

    {
        float z = w2.x * (g_s1[b * NN + pq.x] + g_s2[b * NN + pq.y]);
        z = (z > 0.f) ? z : LRELU_ALPHA * z;
        g_xexp[idx] = fminf(__expf(z), EXP_CLAMP);
        g_rank[idx] = atomicAdd(&g_hist[b * NN + pq.x], 1);
    }
    if (e + 1 < en) {
        float z = w2.y * (g_s1[b * NN + pq.z] + g_s2[b * NN + pq.w]);
        z = (z > 0.f) ? z : LRELU_ALPHA * z;
        g_xexp[idx + 1] = fminf(__expf(z), EXP_CLAMP);
        g_rank[idx + 1] = atomicAdd(&g_hist[b * NN + pq.z], 1);
    }
}

// ---------------------------------------------------------------------------
// Prefix scan of g_hist: 256 blocks x 256 threads; emits 256 block sums.
// ---------------------------------------------------------------------------
__global__ __launch_bounds__(256) void scan1_kernel() {
    __shared__ int wsums[8];
    int i = blockIdx.x * 256 + threadIdx.x;
    int v = g_hist[i];
    int lane = threadIdx.x & 31, w = threadIdx.x >> 5;

    int inc = v;
#pragma unroll
    for (int off = 1; off < 32; off <<= 1) {
        int n = __shfl_up_sync(0xffffffffu, inc, off);
        if (lane >= off) inc += n;
    }
    if (lane == 31) wsums[w] = inc;
    __syncthreads();
    if (threadIdx.x < 32) {
        int s = (threadIdx.x < 8) ? wsums[threadIdx.x] : 0;
#pragma unroll
        for (int off = 1; off < 8; off <<= 1) {
            int n = __shfl_up_sync(0xffffffffu, s, off);
            if (lane >= off) s += n;
        }
        if (threadIdx.x < 8) wsums[threadIdx.x] = s;
    }
    __syncthreads();
    int excl = inc - v + (w > 0 ? wsums[w - 1] : 0);
    g_scan[i] = excl;
    if (threadIdx.x == 255) g_bsum[blockIdx.x] = excl + v;
}

// ---------------------------------------------------------------------------
// Reorder: 2 edges per thread. slot = scan[ctr] + sboff[ctr>>8] + rank.
// ---------------------------------------------------------------------------
__global__ __launch_bounds__(256) void reorder_kernel(
    const int* __restrict__ edge,
    const int* __restrict__ edge_num)
{
    __shared__ int sboff[256];
    scan_bsum_inline(sboff, threadIdx.x);
    __syncthreads();

    int p = blockIdx.x * blockDim.x + threadIdx.x;
    int idx = p * 2;
    int b = idx >> E_SHIFT;
    int e = idx & (EE - 1);
    int en = edge_num[b];
    if (e >= en) return;

    int4 pq = ((const int4*)edge)[p];
    int2 rk = ((const int2*)g_rank)[p];
    float2 xx = ((const float2*)g_xexp)[p];

    {
        int gc = b * NN + pq.x;
        int slot = g_scan[gc] + sboff[gc >> 8] + rk.x;
        g_sorted[slot] = make_int2(b * NN + pq.y, __float_as_int(xx.x));
    }
    if (e + 1 < en) {
        int gc = b * NN + pq.z;
        int slot = g_scan[gc] + sboff[gc >> 8] + rk.y;
        g_sorted[slot] = make_int2(b * NN + pq.w, __float_as_int(xx.y));
    }
}

// ---------------------------------------------------------------------------
// Gather: warp per node (32 lanes x float2). acc = sum x*Wh[nbr], dsum = sum x;
// out = relu(acc/(eps+dsum)). No atomics; one write per element; relu fused.
// Self-clears g_hist for the next graph replay.
// ---------------------------------------------------------------------------
__global__ __launch_bounds__(256) void gather_kernel(float* __restrict__ out) {
    __shared__ int sboff[256];
    scan_bsum_inline(sboff, threadIdx.x);
    __syncthreads();

    int node = blockIdx.x * 8 + (threadIdx.x >> 5);
    int lane = threadIdx.x & 31;
    int start = g_scan[node] + sboff[node >> 8];
    int cnt = g_hist[node];

    float ax = 0.f, ay = 0.f, dsum = 0.f;
#pragma unroll 4
    for (int j = 0; j < cnt; j++) {
        int2 ex = g_sorted[start + j];            // warp-broadcast load
        float x = __int_as_float(ex.y);
        dsum += x;
        float2 wh = *(const float2*)&g_Wh[ex.x * 64 + lane * 2];
        ax += x * wh.x;
        ay += x * wh.y;
    }
    float r = __frcp_rn(DENOM_EPS + dsum);
    float2 v = make_float2(fmaxf(ax * r, 0.f), fmaxf(ay * r, 0.f));
    *(float2*)&out[node * 64 + lane * 2] = v;
    if (lane == 0) g_hist[node] = 0;              // reset for next call
}

// ---------------------------------------------------------------------------
extern "C" void kernel_launch(void* const* d_in, const int* in_sizes, int n_in,
                              void* d_out, int out_size)
{
    const float* h   = (const float*)d_in[0];   // (B,N,F)
    const int*   edge = (const int*)d_in[1];    // (B,E,2)
    const int*   edge_num = (const int*)d_in[2];// (B,)
    const float* ew  = (const float*)d_in[3];   // (B,E)
    const float* W   = (const float*)d_in[4];   // (F,F)
    const float* a   = (const float*)d_in[5];   // (1,2F)
    float* out = (float*)d_out;                 // (B,N,F)

    gemm_kernel<<<NTOT / 64, 256>>>(h, W, a);

    edge_kernel<<<ETOT / 512, 256>>>(edge, edge_num, ew);

    scan1_kernel<<<256, 256>>>();

    reorder_kernel<<<ETOT / 512, 256>>>(edge, edge_num);

    gather_kernel<<<NTOT / 8, 256>>>(out);
}

// round 12
// speedup vs baseline: 2.4661x; 1.0030x over previous
#include <cuda_runtime.h>

// Fixed problem shapes (from reference setup_inputs)
#define BB 4
#define NN 16384
#define EE 262144      // 2^18
#define FF 64
#define E_SHIFT 18
#define NTOT (BB * NN)          // 65536 nodes total
#define ETOT (BB * EE)          // 1,048,576 edge slots

#define EXP_CLAMP 1000000.0f
#define DENOM_EPS 1e-10f
#define LRELU_ALPHA 0.01f

// Scratch (device globals; zero-initialized at load; no allocation allowed)
__device__ float g_Wh[NTOT * FF];        // 16.8 MB
__device__ float g_s1[NTOT];
__device__ float g_s2[NTOT];
__device__ float g_xexp[ETOT];           // 4 MB
__device__ int   g_rank[ETOT];           // 4 MB: rank of edge within its ctr segment
__device__ int   g_hist[NTOT];           // per-node active-edge count (self-cleared by gather)
__device__ int   g_scan[NTOT];           // block-local exclusive scan (256-wide blocks)
__device__ int   g_bsum[256];            // per-scan-block sums
__device__ int2  g_sorted[ETOT];         // {nbr_global, xexp bits} grouped by ctr

// Inline 256-wide exclusive scan of g_bsum into sboff[256] (warp 0 only;
// caller must __syncthreads() after). g_bsum is 1KB, L2-resident.
__device__ __forceinline__ void scan_bsum_inline(int* sboff, int tid) {
    if (tid < 32) {
        int4 v0 = ((const int4*)g_bsum)[tid * 2];
        int4 v1 = ((const int4*)g_bsum)[tid * 2 + 1];
        int s = v0.x + v0.y + v0.z + v0.w + v1.x + v1.y + v1.z + v1.w;
        int inc = s;
#pragma unroll
        for (int off = 1; off < 32; off <<= 1) {
            int n = __shfl_up_sync(0xffffffffu, inc, off);
            if (tid >= off) inc += n;
        }
        int excl = inc - s;
        int base = tid * 8;
        sboff[base + 0] = excl; excl += v0.x;
        sboff[base + 1] = excl; excl += v0.y;
        sboff[base + 2] = excl; excl += v0.z;
        sboff[base + 3] = excl; excl += v0.w;
        sboff[base + 4] = excl; excl += v1.x;
        sboff[base + 5] = excl; excl += v1.y;
        sboff[base + 6] = excl; excl += v1.z;
        sboff[base + 7] = excl;
    }
}

// ---------------------------------------------------------------------------
// GEMM: Wh[b,n,o] = sum_f h[b,n,f] * W[o,f], fused s1/s2 epilogue.
// 64x64 tile per 256-thread block, 4x4 register tile per thread.
// ---------------------------------------------------------------------------
__global__ __launch_bounds__(256) void gemm_kernel(
    const float* __restrict__ h,
    const float* __restrict__ W,
    const float* __restrict__ a)
{
    __shared__ __align__(16) float Wsh[64 * 68];   // [k][o], pad 68
    __shared__ __align__(16) float hshT[64 * 68];  // [k][r] transposed h tile

    const int t = threadIdx.x;
    const int base = blockIdx.x * 64;              // row base within B*N

    for (int i = t; i < 4096; i += 256) {
        int o = i >> 6, k = i & 63;
        Wsh[k * 68 + o] = W[i];
    }
    for (int i = t; i < 4096; i += 256) {
        int r = i >> 6, k = i & 63;
        hshT[k * 68 + r] = h[base * 64 + i];
    }
    __syncthreads();

    const int tx = t & 15, ty = t >> 4;
    const int r0 = ty * 4, c0 = tx * 4;

    float acc[4][4];
#pragma unroll
    for (int i = 0; i < 4; i++)
#pragma unroll
        for (int j = 0; j < 4; j++) acc[i][j] = 0.f;

#pragma unroll
    for (int k = 0; k < 64; k++) {
        float4 av = *(const float4*)&hshT[k * 68 + r0];
        float4 bv = *(const float4*)&Wsh[k * 68 + c0];
        acc[0][0] += av.x * bv.x; acc[0][1] += av.x * bv.y; acc[0][2] += av.x * bv.z; acc[0][3] += av.x * bv.w;
        acc[1][0] += av.y * bv.x; acc[1][1] += av.y * bv.y; acc[1][2] += av.y * bv.z; acc[1][3] += av.y * bv.w;
        acc[2][0] += av.z * bv.x; acc[2][1] += av.z * bv.y; acc[2][2] += av.z * bv.z; acc[2][3] += av.z * bv.w;
        acc[3][0] += av.w * bv.x; acc[3][1] += av.w * bv.y; acc[3][2] += av.w * bv.z; acc[3][3] += av.w * bv.w;
    }

    const float4 a1 = *(const float4*)&a[c0];
    const float4 a2 = *(const float4*)&a[64 + c0];

    float s1v[4], s2v[4];
#pragma unroll
    for (int i = 0; i < 4; i++) {
        int row = base + r0 + i;
        *(float4*)&g_Wh[row * 64 + c0] =
            make_float4(acc[i][0], acc[i][1], acc[i][2], acc[i][3]);
        s1v[i] = acc[i][0] * a1.x + acc[i][1] * a1.y + acc[i][2] * a1.z + acc[i][3] * a1.w;
        s2v[i] = acc[i][0] * a2.x + acc[i][1] * a2.y + acc[i][2] * a2.z + acc[i][3] * a2.w;
    }
#pragma unroll
    for (int off = 8; off > 0; off >>= 1) {
#pragma unroll
        for (int i = 0; i < 4; i++) {
            s1v[i] += __shfl_down_sync(0xffffffffu, s1v[i], off, 16);
            s2v[i] += __shfl_down_sync(0xffffffffu, s2v[i], off, 16);
        }
    }
    if (tx == 0) {
#pragma unroll
        for (int i = 0; i < 4; i++) {
            g_s1[base + r0 + i] = s1v[i];
            g_s2[base + r0 + i] = s2v[i];
        }
    }
}

// ---------------------------------------------------------------------------
// Edge pass: 2 edges per thread (int4/float2 loads). x_exp + ctr histogram;
// atomic's return value = rank in segment.
// ---------------------------------------------------------------------------
__global__ __launch_bounds__(256) void edge_kernel(
    const int* __restrict__ edge,
    const int* __restrict__ edge_num,
    const float* __restrict__ ew)
{
    int p = blockIdx.x * blockDim.x + threadIdx.x;   // pair index
    int idx = p * 2;                                  // EE even -> pair never crosses b
    int b = idx >> E_SHIFT;
    int e = idx & (EE - 1);
    int en = edge_num[b];
    if (e >= en) return;                              // both inactive

    int4 pq = ((const int4*)edge)[p];                 // edge idx: {x,y}, idx+1: {z,w}
    float2 w2 = ((const float2*)ew)[p];

    {
        float z = w2.x * (g_s1[b * NN + pq.x] + g_s2[b * NN + pq.y]);
        z = (z > 0.f) ? z : LRELU_ALPHA * z;
        g_xexp[idx] = fminf(__expf(z), EXP_CLAMP);
        g_rank[idx] = atomicAdd(&g_hist[b * NN + pq.x], 1);
    }
    if (e + 1 < en) {
        float z = w2.y * (g_s1[b * NN + pq.z] + g_s2[b * NN + pq.w]);
        z = (z > 0.f) ? z : LRELU_ALPHA * z;
        g_xexp[idx + 1] = fminf(__expf(z), EXP_CLAMP);
        g_rank[idx + 1] = atomicAdd(&g_hist[b * NN + pq.z], 1);
    }
}

// ---------------------------------------------------------------------------
// Prefix scan of g_hist: 256 blocks x 256 threads; emits 256 block sums.
// ---------------------------------------------------------------------------
__global__ __launch_bounds__(256) void scan1_kernel() {
    __shared__ int wsums[8];
    int i = blockIdx.x * 256 + threadIdx.x;
    int v = g_hist[i];
    int lane = threadIdx.x & 31, w = threadIdx.x >> 5;

    int inc = v;
#pragma unroll
    for (int off = 1; off < 32; off <<= 1) {
        int n = __shfl_up_sync(0xffffffffu, inc, off);
        if (lane >= off) inc += n;
    }
    if (lane == 31) wsums[w] = inc;
    __syncthreads();
    if (threadIdx.x < 32) {
        int s = (threadIdx.x < 8) ? wsums[threadIdx.x] : 0;
#pragma unroll
        for (int off = 1; off < 8; off <<= 1) {
            int n = __shfl_up_sync(0xffffffffu, s, off);
            if (lane >= off) s += n;
        }
        if (threadIdx.x < 8) wsums[threadIdx.x] = s;
    }
    __syncthreads();
    int excl = inc - v + (w > 0 ? wsums[w - 1] : 0);
    g_scan[i] = excl;
    if (threadIdx.x == 255) g_bsum[blockIdx.x] = excl + v;
}

// ---------------------------------------------------------------------------
// Reorder: 2 edges per thread. slot = scan[ctr] + sboff[ctr>>8] + rank.
// ---------------------------------------------------------------------------
__global__ __launch_bounds__(256) void reorder_kernel(
    const int* __restrict__ edge,
    const int* __restrict__ edge_num)
{
    __shared__ int sboff[256];
    scan_bsum_inline(sboff, threadIdx.x);
    __syncthreads();

    int p = blockIdx.x * blockDim.x + threadIdx.x;
    int idx = p * 2;
    int b = idx >> E_SHIFT;
    int e = idx & (EE - 1);
    int en = edge_num[b];
    if (e >= en) return;

    int4 pq = ((const int4*)edge)[p];
    int2 rk = ((const int2*)g_rank)[p];
    float2 xx = ((const float2*)g_xexp)[p];

    {
        int gc = b * NN + pq.x;
        int slot = g_scan[gc] + sboff[gc >> 8] + rk.x;
        g_sorted[slot] = make_int2(b * NN + pq.y, __float_as_int(xx.x));
    }
    if (e + 1 < en) {
        int gc = b * NN + pq.z;
        int slot = g_scan[gc] + sboff[gc >> 8] + rk.y;
        g_sorted[slot] = make_int2(b * NN + pq.w, __float_as_int(xx.y));
    }
}

// ---------------------------------------------------------------------------
// Gather: warp per node (32 lanes x float2). acc = sum x*Wh[nbr], dsum = sum x;
// out = relu(acc/(eps+dsum)). No atomics; one write per element; relu fused.
// Self-clears g_hist for the next graph replay.
// ---------------------------------------------------------------------------
__global__ __launch_bounds__(256) void gather_kernel(float* __restrict__ out) {
    __shared__ int sboff[256];
    scan_bsum_inline(sboff, threadIdx.x);
    __syncthreads();

    int node = blockIdx.x * 8 + (threadIdx.x >> 5);
    int lane = threadIdx.x & 31;
    int start = g_scan[node] + sboff[node >> 8];
    int cnt = g_hist[node];

    float ax = 0.f, ay = 0.f, dsum = 0.f;
#pragma unroll 4
    for (int j = 0; j < cnt; j++) {
        int2 ex = g_sorted[start + j];            // warp-broadcast load
        float x = __int_as_float(ex.y);
        dsum += x;
        float2 wh = *(const float2*)&g_Wh[ex.x * 64 + lane * 2];
        ax += x * wh.x;
        ay += x * wh.y;
    }
    float r = __frcp_rn(DENOM_EPS + dsum);
    float2 v = make_float2(fmaxf(ax * r, 0.f), fmaxf(ay * r, 0.f));
    *(float2*)&out[node * 64 + lane * 2] = v;
    if (lane == 0) g_hist[node] = 0;              // reset for next call
}

// ---------------------------------------------------------------------------
extern "C" void kernel_launch(void* const* d_in, const int* in_sizes, int n_in,
                              void* d_out, int out_size)
{
    const float* h   = (const float*)d_in[0];   // (B,N,F)
    const int*   edge = (const int*)d_in[1];    // (B,E,2)
    const int*   edge_num = (const int*)d_in[2];// (B,)
    const float* ew  = (const float*)d_in[3];   // (B,E)
    const float* W   = (const float*)d_in[4];   // (F,F)
    const float* a   = (const float*)d_in[5];   // (1,2F)
    float* out = (float*)d_out;                 // (B,N,F)

    gemm_kernel<<<NTOT / 64, 256>>>(h, W, a);

    edge_kernel<<<ETOT / 512, 256>>>(edge, edge_num, ew);

    scan1_kernel<<<256, 256>>>();

    reorder_kernel<<<ETOT / 512, 256>>>(edge, edge_num);

    gather_kernel<<<NTOT / 8, 256>>>(out);
}